// round 2
// baseline (speedup 1.0000x reference)
#include <cuda_runtime.h>
#include <math.h>

#define D 256
#define H 8
#define MAXN 50000
#define MAXE 1600000

// -------- scratch (no allocs allowed -> device globals) --------
__device__ float g_q[(size_t)MAXN * D];       // 51.2 MB
__device__ float g_k[(size_t)MAXN * D];       // 51.2 MB
__device__ float g_v[(size_t)MAXN * D];       // 51.2 MB
__device__ float g_attn[(size_t)MAXN * D];    // 51.2 MB
__device__ float g_s[(size_t)MAXE * H];       // 51.2 MB (CSR-ordered scores)
__device__ int   g_cnt[MAXN];
__device__ int   g_ptr[MAXN + 1];
__device__ int   g_fill[MAXN];
__device__ int   g_colbuf[MAXE];

// buffer ids for device-side scratch routing (avoids cudaGetSymbolAddress on host)
#define BUF_EXT  0
#define BUF_Q    1
#define BUF_K    2
#define BUF_V    3
#define BUF_ATTN 4

__device__ __forceinline__ float* buf_ptr(int id, float* ext)
{
    switch (id) {
        case BUF_Q:    return g_q;
        case BUF_K:    return g_k;
        case BUF_V:    return g_v;
        case BUF_ATTN: return g_attn;
        default:       return ext;
    }
}

// ==================== SGEMM: C = alpha * (A @ W + bias) ====================
// A: M x 256 row-major, W: 256 x 256 row-major. BM=128, BN=64, BK=16,
// 256 threads, 8x4 per-thread microtile.
__global__ __launch_bounds__(256) void sgemm_bias_kernel(
    const float* __restrict__ A_ext, int A_id,
    const float* __restrict__ W,
    const float* __restrict__ bias,
    float* __restrict__ C_ext, int C_id,
    int M, float alpha)
{
    const float* A = buf_ptr(A_id, (float*)A_ext);
    float* C = buf_ptr(C_id, C_ext);

    __shared__ __align__(16) float As[16][132];
    __shared__ __align__(16) float Ws[16][64];
    const int tid = threadIdx.x;
    const int tx = tid & 15;   // column group (4 cols)
    const int ty = tid >> 4;   // row group (8 rows)
    const int bm = blockIdx.x * 128;
    const int bn = blockIdx.y * 64;

    float acc[8][4];
#pragma unroll
    for (int i = 0; i < 8; i++)
#pragma unroll
        for (int j = 0; j < 4; j++) acc[i][j] = 0.f;

    for (int k0 = 0; k0 < D; k0 += 16) {
#pragma unroll
        for (int t = 0; t < 2; t++) {
            int slot = tid + t * 256;       // 512 float4 slots for 128x16 A tile
            int r = slot >> 2;
            int cg = (slot & 3) * 4;
            float4 av = make_float4(0.f, 0.f, 0.f, 0.f);
            int gr = bm + r;
            if (gr < M) av = *(const float4*)(A + (size_t)gr * D + k0 + cg);
            As[cg + 0][r] = av.x;
            As[cg + 1][r] = av.y;
            As[cg + 2][r] = av.z;
            As[cg + 3][r] = av.w;
        }
        {
            int r = tid >> 4;
            int cg = (tid & 15) * 4;
            float4 wv = *(const float4*)(W + (size_t)(k0 + r) * D + bn + cg);
            *(float4*)&Ws[r][cg] = wv;
        }
        __syncthreads();
#pragma unroll
        for (int kk = 0; kk < 16; kk++) {
            float4 a0 = *(const float4*)&As[kk][ty * 8];
            float4 a1 = *(const float4*)&As[kk][ty * 8 + 4];
            float4 b  = *(const float4*)&Ws[kk][tx * 4];
            float a[8] = {a0.x, a0.y, a0.z, a0.w, a1.x, a1.y, a1.z, a1.w};
            float bb[4] = {b.x, b.y, b.z, b.w};
#pragma unroll
            for (int i = 0; i < 8; i++)
#pragma unroll
                for (int j = 0; j < 4; j++)
                    acc[i][j] = fmaf(a[i], bb[j], acc[i][j]);
        }
        __syncthreads();
    }
    float4 bv = *(const float4*)(bias + bn + tx * 4);
#pragma unroll
    for (int i = 0; i < 8; i++) {
        int gr = bm + ty * 8 + i;
        if (gr < M) {
            float4 o;
            o.x = (acc[i][0] + bv.x) * alpha;
            o.y = (acc[i][1] + bv.y) * alpha;
            o.z = (acc[i][2] + bv.z) * alpha;
            o.w = (acc[i][3] + bv.w) * alpha;
            *(float4*)(C + (size_t)gr * D + bn + tx * 4) = o;
        }
    }
}

// ==================== CSR build ====================
__global__ void zero_kernel(int n)
{
    int i = blockIdx.x * blockDim.x + threadIdx.x;
    if (i < n) g_cnt[i] = 0;
}

__global__ void hist_kernel(const int* __restrict__ row, int E)
{
    int e = blockIdx.x * blockDim.x + threadIdx.x;
    if (e < E) atomicAdd(&g_cnt[row[e]], 1);
}

// single-block exclusive scan over g_cnt -> g_ptr, g_fill
__global__ void scan_kernel(int n)
{
    __shared__ int warp_sums[32];
    __shared__ int carry;
    const int tid = threadIdx.x;
    const int lane = tid & 31;
    const int wid = tid >> 5;
    if (tid == 0) carry = 0;
    __syncthreads();
    for (int base = 0; base < n; base += 1024) {
        int i = base + tid;
        int v = (i < n) ? g_cnt[i] : 0;
        int x = v;
#pragma unroll
        for (int d = 1; d < 32; d <<= 1) {
            int y = __shfl_up_sync(0xffffffffu, x, d);
            if (lane >= d) x += y;
        }
        if (lane == 31) warp_sums[wid] = x;
        __syncthreads();
        if (wid == 0) {
            int sv = warp_sums[lane];
#pragma unroll
            for (int d = 1; d < 32; d <<= 1) {
                int y = __shfl_up_sync(0xffffffffu, sv, d);
                if (lane >= d) sv += y;
            }
            warp_sums[lane] = sv;
        }
        __syncthreads();
        int prefix = (wid > 0) ? warp_sums[wid - 1] : 0;
        int excl = x - v + prefix + carry;
        if (i < n) { g_ptr[i] = excl; g_fill[i] = excl; }
        int total = warp_sums[31];
        __syncthreads();
        if (tid == 0) carry = carry + total;
        __syncthreads();
    }
    if (tid == 0) g_ptr[n] = carry;
}

__global__ void scatter_kernel(const int* __restrict__ row,
                               const int* __restrict__ col, int E)
{
    int e = blockIdx.x * blockDim.x + threadIdx.x;
    if (e < E) {
        int p = atomicAdd(&g_fill[row[e]], 1);
        g_colbuf[p] = col[e];
    }
}

// ==================== per-node attention: 1 warp / node ====================
// Layout fact (reshape(N, DH, H)): feature d = dh*8 + h. Lane l owns dh = l,
// i.e. contiguous floats [8l, 8l+8) = heads 0..7 at that dh.
//
// Head-interleaved 9-shuffle reduction: after rounds over xor16/8/4 the lane
// holds the full 32-lane sum for head myh = (b2<<2)|(b3<<1)|b4 (each head
// replicated in 4 lanes). Phase 2 re-maps heads as hh = lane&7 so lanes 0..7
// own heads 0..7 for broadcast.
__global__ __launch_bounds__(256) void attn_kernel(int nnodes)
{
    const int lane = threadIdx.x & 31;
    const int node = blockIdx.x * 8 + (threadIdx.x >> 5);
    if (node >= nnodes) return;
    const int start = g_ptr[node];
    const int end = g_ptr[node + 1];

    const int b4 = (lane >> 4) & 1;
    const int b3 = (lane >> 3) & 1;
    const int b2 = (lane >> 2) & 1;
    const int myh = (b2 << 2) | (b3 << 1) | b4;
    const int hh = lane & 7;
    const int owner = ((hh & 1) << 4) | (((hh >> 1) & 1) << 3) | (((hh >> 2) & 1) << 2);

    const float4* qp = (const float4*)(g_q + (size_t)node * D + lane * 8);
    float4 q0 = qp[0], q1 = qp[1];

    float m_local = -1e30f;

    // ---- phase 1: scores + per-head max ----
    for (int base = start; base < end; base += 32) {
        int myj = 0;
        if (base + lane < end) myj = g_colbuf[base + lane];
        int cnt = min(32, end - base);
        for (int t = 0; t < cnt; t++) {
            int j = __shfl_sync(0xffffffffu, myj, t);
            const float4* kp = (const float4*)(g_k + (size_t)j * D + lane * 8);
            float4 k0 = kp[0], k1 = kp[1];
            float p0 = q0.x * k0.x, p1 = q0.y * k0.y, p2 = q0.z * k0.z, p3 = q0.w * k0.w;
            float p4 = q1.x * k1.x, p5 = q1.y * k1.y, p6 = q1.z * k1.z, p7 = q1.w * k1.w;
            float keep, send;
            keep = b4 ? p1 : p0; send = b4 ? p0 : p1;
            float tA0 = keep + __shfl_xor_sync(0xffffffffu, send, 16);
            keep = b4 ? p3 : p2; send = b4 ? p2 : p3;
            float tA1 = keep + __shfl_xor_sync(0xffffffffu, send, 16);
            keep = b4 ? p5 : p4; send = b4 ? p4 : p5;
            float tA2 = keep + __shfl_xor_sync(0xffffffffu, send, 16);
            keep = b4 ? p7 : p6; send = b4 ? p6 : p7;
            float tA3 = keep + __shfl_xor_sync(0xffffffffu, send, 16);
            keep = b3 ? tA1 : tA0; send = b3 ? tA0 : tA1;
            float tB0 = keep + __shfl_xor_sync(0xffffffffu, send, 8);
            keep = b3 ? tA3 : tA2; send = b3 ? tA2 : tA3;
            float tB1 = keep + __shfl_xor_sync(0xffffffffu, send, 8);
            keep = b2 ? tB1 : tB0; send = b2 ? tB0 : tB1;
            float s = keep + __shfl_xor_sync(0xffffffffu, send, 4);
            s += __shfl_xor_sync(0xffffffffu, s, 2);
            s += __shfl_xor_sync(0xffffffffu, s, 1);
            m_local = fmaxf(m_local, s);
            if ((lane & 3) == 0)
                g_s[(size_t)(base + t) * H + myh] = s;
        }
    }
    __threadfence_block();
    __syncwarp();

    // m for my phase-2 head
    float m2 = __shfl_sync(0xffffffffu, m_local, owner);

    // ---- phase 2: exp, z, weighted V accumulation ----
    float acc[8];
#pragma unroll
    for (int i = 0; i < 8; i++) acc[i] = 0.f;
    float z = 0.f;

    for (int base = start; base < end; base += 32) {
        int myj = 0;
        if (base + lane < end) myj = g_colbuf[base + lane];
        int cnt = min(32, end - base);
        for (int t = 0; t < cnt; t++) {
            int j = __shfl_sync(0xffffffffu, myj, t);
            float s = g_s[(size_t)(base + t) * H + hh];
            float w = __expf(s - m2);
            z += w;
            const float4* vp = (const float4*)(g_v + (size_t)j * D + lane * 8);
            float4 v0 = vp[0], v1 = vp[1];
            float vr[8] = {v0.x, v0.y, v0.z, v0.w, v1.x, v1.y, v1.z, v1.w};
#pragma unroll
            for (int i = 0; i < 8; i++) {
                float wi = __shfl_sync(0xffffffffu, w, i);
                acc[i] = fmaf(wi, vr[i], acc[i]);
            }
        }
    }
    float invz = (z > 0.f) ? (1.0f / z) : 0.f;
    float out[8];
#pragma unroll
    for (int i = 0; i < 8; i++)
        out[i] = acc[i] * __shfl_sync(0xffffffffu, invz, i);
    float4* op = (float4*)(g_attn + (size_t)node * D + lane * 8);
    op[0] = make_float4(out[0], out[1], out[2], out[3]);
    op[1] = make_float4(out[4], out[5], out[6], out[7]);
}

// ==================== launch ====================
extern "C" void kernel_launch(void* const* d_in, const int* in_sizes, int n_in,
                              void* d_out, int out_size)
{
    const float* x  = (const float*)d_in[0];
    const int*   row = (const int*)d_in[1];
    const int*   col = (const int*)d_in[2];
    const float* Wq = (const float*)d_in[3];
    const float* bq = (const float*)d_in[4];
    const float* Wk = (const float*)d_in[5];
    const float* bk = (const float*)d_in[6];
    const float* Wv = (const float*)d_in[7];
    const float* bv = (const float*)d_in[8];
    const float* Wo = (const float*)d_in[9];
    const float* bo = (const float*)d_in[10];
    float* out = (float*)d_out;

    const int N = in_sizes[0] / D;
    const int E = in_sizes[1];
    const float scaling = 0.17677669529663687f; // 32^-0.5

    // CSR build
    zero_kernel<<<(N + 255) / 256, 256>>>(N);
    hist_kernel<<<(E + 255) / 256, 256>>>(row, E);
    scan_kernel<<<1, 1024>>>(N);
    scatter_kernel<<<(E + 255) / 256, 256>>>(row, col, E);

    // projections (scaling folded into Q); scratch routed by buffer id
    dim3 ggrid((N + 127) / 128, D / 64);
    sgemm_bias_kernel<<<ggrid, 256>>>(x, BUF_EXT, Wq, bq, nullptr, BUF_Q, N, scaling);
    sgemm_bias_kernel<<<ggrid, 256>>>(x, BUF_EXT, Wk, bk, nullptr, BUF_K, N, 1.f);
    sgemm_bias_kernel<<<ggrid, 256>>>(x, BUF_EXT, Wv, bv, nullptr, BUF_V, N, 1.f);

    // sparse attention (1 warp / node)
    attn_kernel<<<(N + 7) / 8, 256>>>(N);

    // output projection
    sgemm_bias_kernel<<<ggrid, 256>>>(nullptr, BUF_ATTN, Wo, bo, out, BUF_EXT, N, 1.f);
}